// round 4
// baseline (speedup 1.0000x reference)
#include <cuda_runtime.h>
#include <cstdint>

#define NB 2
#define NH 12
#define SQ 2048
#define DH 64
#define DM 768
#define SCALE 0.125f

// Scratch for Q/K/V in [B, H, S, Dh] layout (device globals: allocation-free rule)
__device__ float g_q[NB * NH * SQ * DH];
__device__ float g_k[NB * NH * SQ * DH];
__device__ float g_v[NB * NH * SQ * DH];

__device__ __forceinline__ uint32_t f2tf(float f) {
    uint32_t u;
    asm("cvt.rna.tf32.f32 %0, %1;" : "=r"(u) : "f"(f));
    return u;
}

__device__ __forceinline__ uint4 cvt4(float4 v) {
    return make_uint4(f2tf(v.x), f2tf(v.y), f2tf(v.z), f2tf(v.w));
}

__device__ __forceinline__ void mma8(float* c, const uint32_t* a, const uint32_t* b) {
    asm volatile(
        "mma.sync.aligned.m16n8k8.row.col.f32.tf32.tf32.f32 "
        "{%0,%1,%2,%3}, {%4,%5,%6,%7}, {%8,%9}, {%0,%1,%2,%3};\n"
        : "+f"(c[0]), "+f"(c[1]), "+f"(c[2]), "+f"(c[3])
        : "r"(a[0]), "r"(a[1]), "r"(a[2]), "r"(a[3]), "r"(b[0]), "r"(b[1]));
}

// ---------------------------------------------------------------------------
// Kernel 1: fused QKV projection.  out[m,n] = X[m,:] . W[n,:] + bias[n]
// M=4096, N=768, K=768.  BM=128, BN=64, BK=32. 8 warps (4x2), warp 32x32.
// k within each group of 8 is logically permuted (lane q <-> cols 2q,2q+1)
// identically on A and B so fragment pairs are contiguous -> LDS.64.
// Register-prefetch of next k-slice overlaps the mma section.
// ---------------------------------------------------------------------------
__global__ __launch_bounds__(256, 2) void qkv_kernel(
    const float* __restrict__ X,
    const float* __restrict__ Wq, const float* __restrict__ bq,
    const float* __restrict__ Wk, const float* __restrict__ bk,
    const float* __restrict__ Wv, const float* __restrict__ bv)
{
    const float* W;
    const float* bias;
    float* out;
    if (blockIdx.z == 0)      { W = Wq; bias = bq; out = g_q; }
    else if (blockIdx.z == 1) { W = Wk; bias = bk; out = g_k; }
    else                      { W = Wv; bias = bv; out = g_v; }

    __shared__ uint32_t As[128][40];  // [m][k] tf32 bits (pad 8: conflict-free LDS.64)
    __shared__ uint32_t Bs[64][40];   // [n][k] tf32 bits

    const int tid  = threadIdx.x;
    const int lane = tid & 31;
    const int warp = tid >> 5;
    const int wm   = warp >> 1;
    const int wn   = warp & 1;
    const int m0   = blockIdx.y * 128;
    const int n0   = blockIdx.x * 64;
    const int q4   = lane & 3;
    const int r4   = lane >> 2;

    float acc[2][4][4];
    #pragma unroll
    for (int i = 0; i < 2; i++)
        #pragma unroll
        for (int j = 0; j < 4; j++)
            #pragma unroll
            for (int e = 0; e < 4; e++) acc[i][j][e] = 0.f;

    const int ar = tid >> 3;        // 0..31
    const int ac = (tid & 7) * 4;   // 0..28

    const float* Xb = X + (size_t)(m0 + ar) * DM + ac;
    const float* Wb = W + (size_t)(n0 + ar) * DM + ac;

    float4 xr[4], wr[2];
    #pragma unroll
    for (int it = 0; it < 4; it++) xr[it] = *(const float4*)(Xb + (size_t)it * 32 * DM);
    #pragma unroll
    for (int it = 0; it < 2; it++) wr[it] = *(const float4*)(Wb + (size_t)it * 32 * DM);

    for (int kt = 0; kt < 24; kt++) {
        #pragma unroll
        for (int it = 0; it < 4; it++) *(uint4*)&As[ar + it * 32][ac] = cvt4(xr[it]);
        #pragma unroll
        for (int it = 0; it < 2; it++) *(uint4*)&Bs[ar + it * 32][ac] = cvt4(wr[it]);
        __syncthreads();
        if (kt < 23) {
            const float* Xn = Xb + (kt + 1) * 32;
            const float* Wn = Wb + (kt + 1) * 32;
            #pragma unroll
            for (int it = 0; it < 4; it++) xr[it] = *(const float4*)(Xn + (size_t)it * 32 * DM);
            #pragma unroll
            for (int it = 0; it < 2; it++) wr[it] = *(const float4*)(Wn + (size_t)it * 32 * DM);
        }
        #pragma unroll
        for (int kk = 0; kk < 4; kk++) {
            const int c = kk * 8 + 2 * q4;
            uint32_t a[2][4];
            #pragma unroll
            for (int i = 0; i < 2; i++) {
                int r = wm * 32 + i * 16 + r4;
                uint2 lo = *(const uint2*)&As[r][c];
                uint2 hi = *(const uint2*)&As[r + 8][c];
                a[i][0] = lo.x; a[i][1] = hi.x; a[i][2] = lo.y; a[i][3] = hi.y;
            }
            #pragma unroll
            for (int j = 0; j < 4; j++) {
                int cc = wn * 32 + j * 8 + r4;
                uint2 bp = *(const uint2*)&Bs[cc][c];
                uint32_t b2[2] = {bp.x, bp.y};
                #pragma unroll
                for (int i = 0; i < 2; i++) mma8(acc[i][j], a[i], b2);
            }
        }
        __syncthreads();
    }

    // Epilogue: +bias, store to [B,H,S,Dh]
    #pragma unroll
    for (int i = 0; i < 2; i++) {
        #pragma unroll
        for (int j = 0; j < 4; j++) {
            int n  = n0 + wn * 32 + j * 8 + 2 * q4;
            int h  = n >> 6;
            int dh = n & 63;
            float b0 = bias[n], b1 = bias[n + 1];
            #pragma unroll
            for (int rr = 0; rr < 2; rr++) {
                int m  = m0 + wm * 32 + i * 16 + r4 + rr * 8;
                int bb = m >> 11;
                int s  = m & 2047;
                size_t idx = (((size_t)(bb * NH + h)) * SQ + s) * DH + dh;
                out[idx]     = acc[i][j][rr * 2 + 0] + b0;
                out[idx + 1] = acc[i][j][rr * 2 + 1] + b1;
            }
        }
    }
}

// ---------------------------------------------------------------------------
// Kernel 2: flash-style attention with RealFormer residual.
// Grid: (S/128, H, B). 8 warps; warp w owns q rows [128*bx + 16w, +16).
// Double-buffered K/V smem, register prefetch of next chunk, ONE barrier/iter.
// k-permuted fragments: QK B and PV a / sP are LDS.64/STS.64.
// Pads: sK rows 72, sV rows 68, sP rows 40 (conflict-free per access pattern).
// ---------------------------------------------------------------------------
#define SK_ROW 72
#define SV_ROW 68
#define SP_ROW 40
#define SK_BUF (32 * SK_ROW)
#define SV_BUF (32 * SV_ROW)
#define ATTN_SMEM ((2 * SK_BUF + 2 * SV_BUF + 8 * 16 * SP_ROW) * 4)

__global__ __launch_bounds__(256, 2) void attn_kernel(
    const float* __restrict__ res_in,
    const float* __restrict__ mask,
    float* __restrict__ ctx_out,
    float* __restrict__ res_out)
{
    extern __shared__ uint32_t dyn[];
    uint32_t* sKb = dyn;                          // [2][32][72]
    uint32_t* sVb = dyn + 2 * SK_BUF;             // [2][32][68]
    uint32_t* sPb = dyn + 2 * SK_BUF + 2 * SV_BUF; // [8][16][40]

    const int tid  = threadIdx.x;
    const int lane = tid & 31;
    const int warp = tid >> 5;
    const int q4   = lane & 3;
    const int r4   = lane >> 2;
    const int h  = blockIdx.y;
    const int b  = blockIdx.z;
    const int bh = b * NH + h;
    const int q0 = blockIdx.x * 128;

    const float* Q = g_q + (size_t)bh * SQ * DH;
    const float* K = g_k + (size_t)bh * SQ * DH;
    const float* V = g_v + (size_t)bh * SQ * DH;

    const int lr = tid >> 4;          // 0..15
    const int lc = (tid & 15) * 4;    // 0..60

    // prologue: prefetch chunk 0 K/V
    float4 pk0 = *(const float4*)&K[(size_t)lr * DH + lc];
    float4 pk1 = *(const float4*)&K[(size_t)(lr + 16) * DH + lc];
    float4 pv0 = *(const float4*)&V[(size_t)lr * DH + lc];
    float4 pv1 = *(const float4*)&V[(size_t)(lr + 16) * DH + lc];

    // Q fragments, permuted k within groups of 8 (lane q -> cols 2q, 2q+1)
    uint32_t qf[8][4];
    {
        int r0 = q0 + warp * 16 + r4;
        const float* Qr0 = Q + (size_t)r0 * DH;
        const float* Qr8 = Qr0 + 8 * DH;
        #pragma unroll
        for (int kk = 0; kk < 8; kk++) {
            int c = kk * 8 + 2 * q4;
            qf[kk][0] = f2tf(Qr0[c]);
            qf[kk][1] = f2tf(Qr8[c]);
            qf[kk][2] = f2tf(Qr0[c + 1]);
            qf[kk][3] = f2tf(Qr8[c + 1]);
        }
    }

    *(uint4*)&sKb[lr * SK_ROW + lc]        = cvt4(pk0);
    *(uint4*)&sKb[(lr + 16) * SK_ROW + lc] = cvt4(pk1);
    *(uint4*)&sVb[lr * SV_ROW + lc]        = cvt4(pv0);
    *(uint4*)&sVb[(lr + 16) * SV_ROW + lc] = cvt4(pv1);
    __syncthreads();

    float Oacc[8][4];
    #pragma unroll
    for (int f = 0; f < 8; f++)
        #pragma unroll
        for (int e = 0; e < 4; e++) Oacc[f][e] = 0.f;
    float mrow0 = -1e30f, mrow1 = -1e30f;
    float lrow0 = 0.f, lrow1 = 0.f;

    const int rq0 = q0 + warp * 16 + r4;
    const size_t res0 = ((size_t)bh * SQ + rq0) * SQ;
    const size_t res8 = res0 + (size_t)8 * SQ;
    const float* mrk = mask + b * SQ;
    uint32_t* sPw = sPb + warp * 16 * SP_ROW;

    for (int j = 0; j < SQ / 32; j++) {
        const int cur = j & 1;
        const uint32_t* sK = sKb + cur * SK_BUF;
        const uint32_t* sV = sVb + cur * SV_BUF;

        // prefetch next chunk K/V into registers (latency hidden by compute)
        if (j < SQ / 32 - 1) {
            const float* Kn = K + (size_t)(j + 1) * 32 * DH;
            const float* Vn = V + (size_t)(j + 1) * 32 * DH;
            pk0 = *(const float4*)&Kn[(size_t)lr * DH + lc];
            pk1 = *(const float4*)&Kn[(size_t)(lr + 16) * DH + lc];
            pv0 = *(const float4*)&Vn[(size_t)lr * DH + lc];
            pv1 = *(const float4*)&Vn[(size_t)(lr + 16) * DH + lc];
        }

        // S = Q . K^T  (m16 x n32, k=64), B pairs contiguous -> LDS.64
        float s[4][4];
        #pragma unroll
        for (int f = 0; f < 4; f++)
            #pragma unroll
            for (int e = 0; e < 4; e++) s[f][e] = 0.f;
        #pragma unroll
        for (int kk = 0; kk < 8; kk++) {
            const int c = kk * 8 + 2 * q4;
            #pragma unroll
            for (int f = 0; f < 4; f++) {
                int key = f * 8 + r4;
                uint2 bp = *(const uint2*)&sK[key * SK_ROW + c];
                uint32_t b2[2] = {bp.x, bp.y};
                mma8(s[f], qf[kk], b2);
            }
        }

        const int kb = j * 32;
        // scale + residual (streaming), write scores_res_out pre-mask, then +mask
        #pragma unroll
        for (int f = 0; f < 4; f++) {
            int col = kb + f * 8 + 2 * q4;
            float2 r0v = __ldcs((const float2*)&res_in[res0 + col]);
            float2 r8v = __ldcs((const float2*)&res_in[res8 + col]);
            s[f][0] = s[f][0] * SCALE + r0v.x;
            s[f][1] = s[f][1] * SCALE + r0v.y;
            s[f][2] = s[f][2] * SCALE + r8v.x;
            s[f][3] = s[f][3] * SCALE + r8v.y;
            __stcs((float2*)&res_out[res0 + col], make_float2(s[f][0], s[f][1]));
            __stcs((float2*)&res_out[res8 + col], make_float2(s[f][2], s[f][3]));
            float2 mk = *(const float2*)&mrk[col];
            s[f][0] += mk.x; s[f][1] += mk.y;
            s[f][2] += mk.x; s[f][3] += mk.y;
        }

        // online softmax (rows within a quad: shfl xor 1,2)
        float cmax0 = -1e30f, cmax1 = -1e30f;
        #pragma unroll
        for (int f = 0; f < 4; f++) {
            cmax0 = fmaxf(cmax0, fmaxf(s[f][0], s[f][1]));
            cmax1 = fmaxf(cmax1, fmaxf(s[f][2], s[f][3]));
        }
        cmax0 = fmaxf(cmax0, __shfl_xor_sync(0xffffffff, cmax0, 1));
        cmax0 = fmaxf(cmax0, __shfl_xor_sync(0xffffffff, cmax0, 2));
        cmax1 = fmaxf(cmax1, __shfl_xor_sync(0xffffffff, cmax1, 1));
        cmax1 = fmaxf(cmax1, __shfl_xor_sync(0xffffffff, cmax1, 2));
        float nm0 = fmaxf(mrow0, cmax0);
        float nm1 = fmaxf(mrow1, cmax1);
        float corr0 = __expf(mrow0 - nm0);
        float corr1 = __expf(mrow1 - nm1);
        mrow0 = nm0; mrow1 = nm1;

        float sum0 = 0.f, sum1 = 0.f;
        #pragma unroll
        for (int f = 0; f < 4; f++) {
            s[f][0] = __expf(s[f][0] - nm0);
            s[f][1] = __expf(s[f][1] - nm0);
            s[f][2] = __expf(s[f][2] - nm1);
            s[f][3] = __expf(s[f][3] - nm1);
            sum0 += s[f][0] + s[f][1];
            sum1 += s[f][2] + s[f][3];
        }
        sum0 += __shfl_xor_sync(0xffffffff, sum0, 1);
        sum0 += __shfl_xor_sync(0xffffffff, sum0, 2);
        sum1 += __shfl_xor_sync(0xffffffff, sum1, 1);
        sum1 += __shfl_xor_sync(0xffffffff, sum1, 2);
        lrow0 = lrow0 * corr0 + sum0;
        lrow1 = lrow1 * corr1 + sum1;
        #pragma unroll
        for (int f = 0; f < 8; f++) {
            Oacc[f][0] *= corr0; Oacc[f][1] *= corr0;
            Oacc[f][2] *= corr1; Oacc[f][3] *= corr1;
        }

        // P -> smem (STS.64, per-warp region)
        #pragma unroll
        for (int f = 0; f < 4; f++) {
            int c = f * 8 + 2 * q4;
            *(uint2*)&sPw[r4 * SP_ROW + c]       = make_uint2(f2tf(s[f][0]), f2tf(s[f][1]));
            *(uint2*)&sPw[(r4 + 8) * SP_ROW + c] = make_uint2(f2tf(s[f][2]), f2tf(s[f][3]));
        }
        __syncwarp();

        // O += P . V  (k-permuted: lane q consumes keys 2q, 2q+1 per group)
        #pragma unroll
        for (int kk = 0; kk < 4; kk++) {
            const int pc = kk * 8 + 2 * q4;
            uint2 a01 = *(const uint2*)&sPw[r4 * SP_ROW + pc];
            uint2 a23 = *(const uint2*)&sPw[(r4 + 8) * SP_ROW + pc];
            uint32_t a[4] = {a01.x, a23.x, a01.y, a23.y};
            const int kr = kk * 8 + 2 * q4;
            #pragma unroll
            for (int f = 0; f < 8; f++) {
                int nc = f * 8 + r4;
                uint32_t b2[2] = { sV[kr * SV_ROW + nc], sV[(kr + 1) * SV_ROW + nc] };
                mma8(Oacc[f], a, b2);
            }
        }

        // write next chunk into the other buffer, single barrier per iteration
        if (j < SQ / 32 - 1) {
            const int nxt = cur ^ 1;
            *(uint4*)&sKb[nxt * SK_BUF + lr * SK_ROW + lc]        = cvt4(pk0);
            *(uint4*)&sKb[nxt * SK_BUF + (lr + 16) * SK_ROW + lc] = cvt4(pk1);
            *(uint4*)&sVb[nxt * SV_BUF + lr * SV_ROW + lc]        = cvt4(pv0);
            *(uint4*)&sVb[nxt * SV_BUF + (lr + 16) * SV_ROW + lc] = cvt4(pv1);
        }
        __syncthreads();
    }

    // Epilogue: O / l, store ctx [B, S, H*Dh]
    float inv0 = 1.f / lrow0;
    float inv1 = 1.f / lrow1;
    int row0 = q0 + warp * 16 + r4;
    #pragma unroll
    for (int f = 0; f < 8; f++) {
        int dh = f * 8 + 2 * q4;
        size_t i0 = ((size_t)b * SQ + row0) * DM + h * DH + dh;
        size_t i8 = ((size_t)b * SQ + row0 + 8) * DM + h * DH + dh;
        *(float2*)&ctx_out[i0] = make_float2(Oacc[f][0] * inv0, Oacc[f][1] * inv0);
        *(float2*)&ctx_out[i8] = make_float2(Oacc[f][2] * inv1, Oacc[f][3] * inv1);
    }
}

extern "C" void kernel_launch(void* const* d_in, const int* in_sizes, int n_in,
                              void* d_out, int out_size) {
    const float* X    = (const float*)d_in[0];
    const float* mask = (const float*)d_in[1];
    const float* res  = (const float*)d_in[2];
    const float* Wq   = (const float*)d_in[3];
    const float* bq   = (const float*)d_in[4];
    const float* Wk   = (const float*)d_in[5];
    const float* bk   = (const float*)d_in[6];
    const float* Wv   = (const float*)d_in[7];
    const float* bv   = (const float*)d_in[8];

    float* ctx     = (float*)d_out;
    float* res_out = (float*)d_out + (size_t)NB * SQ * DM;

    cudaFuncSetAttribute(attn_kernel, cudaFuncAttributeMaxDynamicSharedMemorySize, ATTN_SMEM);

    dim3 g1(DM / 64, (NB * SQ) / 128, 3);
    qkv_kernel<<<g1, 256>>>(X, Wq, bq, Wk, bk, Wv, bv);

    dim3 g2(SQ / 128, NH, NB);
    attn_kernel<<<g2, 256, ATTN_SMEM>>>(res, mask, ctx, res_out);
}

// round 5
// speedup vs baseline: 1.2945x; 1.2945x over previous
#include <cuda_runtime.h>
#include <cstdint>

#define NB 2
#define NH 12
#define SQ 2048
#define DH 64
#define DM 768
#define SCALE 0.125f

// Scratch for Q/K/V in [B, H, S, Dh] layout (device globals: allocation-free rule)
__device__ float g_q[NB * NH * SQ * DH];
__device__ float g_k[NB * NH * SQ * DH];
__device__ float g_v[NB * NH * SQ * DH];

__device__ __forceinline__ uint32_t f2tf(float f) {
    uint32_t u;
    asm("cvt.rna.tf32.f32 %0, %1;" : "=r"(u) : "f"(f));
    return u;
}

__device__ __forceinline__ uint4 cvt4(float4 v) {
    return make_uint4(f2tf(v.x), f2tf(v.y), f2tf(v.z), f2tf(v.w));
}

__device__ __forceinline__ void mma8(float* c, const uint32_t* a, const uint32_t* b) {
    asm volatile(
        "mma.sync.aligned.m16n8k8.row.col.f32.tf32.tf32.f32 "
        "{%0,%1,%2,%3}, {%4,%5,%6,%7}, {%8,%9}, {%0,%1,%2,%3};\n"
        : "+f"(c[0]), "+f"(c[1]), "+f"(c[2]), "+f"(c[3])
        : "r"(a[0]), "r"(a[1]), "r"(a[2]), "r"(a[3]), "r"(b[0]), "r"(b[1]));
}

// ---------------------------------------------------------------------------
// Kernel 1: fused QKV projection (R3 version).  out[m,n] = X[m,:].W[n,:]+b[n]
// M=4096, N=768, K=768.  BM=128, BN=64, BK=32. 8 warps (4x2), warp 32x32.
// ---------------------------------------------------------------------------
__global__ __launch_bounds__(256) void qkv_kernel(
    const float* __restrict__ X,
    const float* __restrict__ Wq, const float* __restrict__ bq,
    const float* __restrict__ Wk, const float* __restrict__ bk,
    const float* __restrict__ Wv, const float* __restrict__ bv)
{
    const float* W;
    const float* bias;
    float* out;
    if (blockIdx.z == 0)      { W = Wq; bias = bq; out = g_q; }
    else if (blockIdx.z == 1) { W = Wk; bias = bk; out = g_k; }
    else                      { W = Wv; bias = bv; out = g_v; }

    __shared__ uint32_t As[128][36];
    __shared__ uint32_t Bs[64][36];

    const int tid  = threadIdx.x;
    const int lane = tid & 31;
    const int warp = tid >> 5;
    const int wm   = warp >> 1;
    const int wn   = warp & 1;
    const int m0   = blockIdx.y * 128;
    const int n0   = blockIdx.x * 64;

    float acc[2][4][4];
    #pragma unroll
    for (int i = 0; i < 2; i++)
        #pragma unroll
        for (int j = 0; j < 4; j++)
            #pragma unroll
            for (int e = 0; e < 4; e++) acc[i][j][e] = 0.f;

    const int ar = tid >> 3;
    const int ac = (tid & 7) * 4;

    for (int kt = 0; kt < DM / 32; kt++) {
        const int k0 = kt * 32;
        #pragma unroll
        for (int it = 0; it < 4; it++) {
            int r = ar + it * 32;
            float4 v = *(const float4*)&X[(size_t)(m0 + r) * DM + k0 + ac];
            *(uint4*)&As[r][ac] = cvt4(v);
        }
        #pragma unroll
        for (int it = 0; it < 2; it++) {
            int r = ar + it * 32;
            float4 v = *(const float4*)&W[(size_t)(n0 + r) * DM + k0 + ac];
            *(uint4*)&Bs[r][ac] = cvt4(v);
        }
        __syncthreads();
        #pragma unroll
        for (int kk = 0; kk < 4; kk++) {
            uint32_t a[2][4], b[4][2];
            #pragma unroll
            for (int i = 0; i < 2; i++) {
                int r = wm * 32 + i * 16 + (lane >> 2);
                int c = kk * 8 + (lane & 3);
                a[i][0] = As[r][c];
                a[i][1] = As[r + 8][c];
                a[i][2] = As[r][c + 4];
                a[i][3] = As[r + 8][c + 4];
            }
            #pragma unroll
            for (int j = 0; j < 4; j++) {
                int cc = wn * 32 + j * 8 + (lane >> 2);
                int c  = kk * 8 + (lane & 3);
                b[j][0] = Bs[cc][c];
                b[j][1] = Bs[cc][c + 4];
            }
            #pragma unroll
            for (int i = 0; i < 2; i++)
                #pragma unroll
                for (int j = 0; j < 4; j++)
                    mma8(acc[i][j], a[i], b[j]);
        }
        __syncthreads();
    }

    #pragma unroll
    for (int i = 0; i < 2; i++) {
        #pragma unroll
        for (int j = 0; j < 4; j++) {
            int n  = n0 + wn * 32 + j * 8 + 2 * (lane & 3);
            int h  = n >> 6;
            int dh = n & 63;
            float b0 = bias[n], b1 = bias[n + 1];
            #pragma unroll
            for (int rr = 0; rr < 2; rr++) {
                int m  = m0 + wm * 32 + i * 16 + (lane >> 2) + rr * 8;
                int bb = m >> 11;
                int s  = m & 2047;
                size_t idx = (((size_t)(bb * NH + h)) * SQ + s) * DH + dh;
                out[idx]     = acc[i][j][rr * 2 + 0] + b0;
                out[idx + 1] = acc[i][j][rr * 2 + 1] + b1;
            }
        }
    }
}

// ---------------------------------------------------------------------------
// Kernel 2: flash-style attention with RealFormer residual.
// Grid: (S/128, H, B). 8 warps; warp w owns q rows [128*bx + 16w, +16).
// R3 single-buffer two-barrier K/V structure. k-permuted fragments:
//  - QK B-frags: LDS.64 from sK (row stride 72: conflict-free in 16-lane
//    double-bank phases: dbank = 4*r4 + q4 distinct).
//  - PV A-frags: DIRECT from QK C registers (s[kk]) -- no sP round trip.
// Residual loads hoisted to chunk top (latency overlaps STS+barrier+QK).
// ---------------------------------------------------------------------------
#define SK_ROW 72
#define SV_ROW 68

__global__ __launch_bounds__(256, 2) void attn_kernel(
    const float* __restrict__ res_in,
    const float* __restrict__ mask,
    float* __restrict__ ctx_out,
    float* __restrict__ res_out)
{
    __shared__ uint32_t sK[32 * SK_ROW];
    __shared__ uint32_t sV[32 * SV_ROW];

    const int tid  = threadIdx.x;
    const int lane = tid & 31;
    const int warp = tid >> 5;
    const int q4   = lane & 3;
    const int r4   = lane >> 2;
    const int h  = blockIdx.y;
    const int b  = blockIdx.z;
    const int bh = b * NH + h;
    const int q0 = blockIdx.x * 128;

    const float* Q = g_q + (size_t)bh * SQ * DH;
    const float* K = g_k + (size_t)bh * SQ * DH;
    const float* V = g_v + (size_t)bh * SQ * DH;

    // Q fragments, permuted k within groups of 8 (lane q -> cols 2q, 2q+1)
    uint32_t qf[8][4];
    {
        int r0 = q0 + warp * 16 + r4;
        const float* Qr0 = Q + (size_t)r0 * DH;
        const float* Qr8 = Qr0 + 8 * DH;
        #pragma unroll
        for (int kk = 0; kk < 8; kk++) {
            int c = kk * 8 + 2 * q4;
            qf[kk][0] = f2tf(Qr0[c]);
            qf[kk][1] = f2tf(Qr8[c]);
            qf[kk][2] = f2tf(Qr0[c + 1]);
            qf[kk][3] = f2tf(Qr8[c + 1]);
        }
    }

    float Oacc[8][4];
    #pragma unroll
    for (int f = 0; f < 8; f++)
        #pragma unroll
        for (int e = 0; e < 4; e++) Oacc[f][e] = 0.f;
    float mrow0 = -1e30f, mrow1 = -1e30f;
    float lrow0 = 0.f, lrow1 = 0.f;

    const int rq0 = q0 + warp * 16 + r4;
    const size_t res0 = ((size_t)bh * SQ + rq0) * SQ;
    const size_t res8 = res0 + (size_t)8 * SQ;
    const float* mrk = mask + b * SQ;

    const int lr = tid >> 4;          // 0..15
    const int lc = (tid & 15) * 4;    // 0..60

    for (int j = 0; j < SQ / 32; j++) {
        const int kb = j * 32;
        __syncthreads();   // previous chunk's reads of sK/sV done

        // Residual loads for THIS chunk: independent of smem -> issue first,
        // latency overlaps K/V load+STS+barrier+QK mma.
        float2 rin0[4], rin8[4];
        #pragma unroll
        for (int f = 0; f < 4; f++) {
            int col = kb + f * 8 + 2 * q4;
            rin0[f] = __ldcs((const float2*)&res_in[res0 + col]);
            rin8[f] = __ldcs((const float2*)&res_in[res8 + col]);
        }

        // Load K,V chunk (32 keys x 64 dh each), coalesced float4
        {
            #pragma unroll
            for (int it = 0; it < 2; it++) {
                int key = lr + it * 16;
                float4 kv = *(const float4*)&K[(size_t)(kb + key) * DH + lc];
                *(uint4*)&sK[key * SK_ROW + lc] = cvt4(kv);
                float4 vv = *(const float4*)&V[(size_t)(kb + key) * DH + lc];
                *(uint4*)&sV[key * SV_ROW + lc] = cvt4(vv);
            }
        }
        __syncthreads();

        // S = Q . K^T  (m16 x n32, k=64), B pairs contiguous -> LDS.64
        float s[4][4];
        #pragma unroll
        for (int f = 0; f < 4; f++)
            #pragma unroll
            for (int e = 0; e < 4; e++) s[f][e] = 0.f;
        #pragma unroll
        for (int kk = 0; kk < 8; kk++) {
            const int c = kk * 8 + 2 * q4;
            #pragma unroll
            for (int f = 0; f < 4; f++) {
                int key = f * 8 + r4;
                uint2 bp = *(const uint2*)&sK[key * SK_ROW + c];
                uint32_t b2[2] = {bp.x, bp.y};
                mma8(s[f], qf[kk], b2);
            }
        }

        // scale + residual, write scores_res_out pre-mask, then +mask
        #pragma unroll
        for (int f = 0; f < 4; f++) {
            int col = kb + f * 8 + 2 * q4;
            s[f][0] = s[f][0] * SCALE + rin0[f].x;
            s[f][1] = s[f][1] * SCALE + rin0[f].y;
            s[f][2] = s[f][2] * SCALE + rin8[f].x;
            s[f][3] = s[f][3] * SCALE + rin8[f].y;
            __stcs((float2*)&res_out[res0 + col], make_float2(s[f][0], s[f][1]));
            __stcs((float2*)&res_out[res8 + col], make_float2(s[f][2], s[f][3]));
            float2 mk = *(const float2*)&mrk[col];
            s[f][0] += mk.x; s[f][1] += mk.y;
            s[f][2] += mk.x; s[f][3] += mk.y;
        }

        // online softmax (rows within a quad: shfl xor 1,2)
        float cmax0 = -1e30f, cmax1 = -1e30f;
        #pragma unroll
        for (int f = 0; f < 4; f++) {
            cmax0 = fmaxf(cmax0, fmaxf(s[f][0], s[f][1]));
            cmax1 = fmaxf(cmax1, fmaxf(s[f][2], s[f][3]));
        }
        cmax0 = fmaxf(cmax0, __shfl_xor_sync(0xffffffff, cmax0, 1));
        cmax0 = fmaxf(cmax0, __shfl_xor_sync(0xffffffff, cmax0, 2));
        cmax1 = fmaxf(cmax1, __shfl_xor_sync(0xffffffff, cmax1, 1));
        cmax1 = fmaxf(cmax1, __shfl_xor_sync(0xffffffff, cmax1, 2));
        float nm0 = fmaxf(mrow0, cmax0);
        float nm1 = fmaxf(mrow1, cmax1);
        float corr0 = __expf(mrow0 - nm0);
        float corr1 = __expf(mrow1 - nm1);
        mrow0 = nm0; mrow1 = nm1;

        float sum0 = 0.f, sum1 = 0.f;
        #pragma unroll
        for (int f = 0; f < 4; f++) {
            s[f][0] = __expf(s[f][0] - nm0);
            s[f][1] = __expf(s[f][1] - nm0);
            s[f][2] = __expf(s[f][2] - nm1);
            s[f][3] = __expf(s[f][3] - nm1);
            sum0 += s[f][0] + s[f][1];
            sum1 += s[f][2] + s[f][3];
        }
        sum0 += __shfl_xor_sync(0xffffffff, sum0, 1);
        sum0 += __shfl_xor_sync(0xffffffff, sum0, 2);
        sum1 += __shfl_xor_sync(0xffffffff, sum1, 1);
        sum1 += __shfl_xor_sync(0xffffffff, sum1, 2);
        lrow0 = lrow0 * corr0 + sum0;
        lrow1 = lrow1 * corr1 + sum1;
        #pragma unroll
        for (int f = 0; f < 8; f++) {
            Oacc[f][0] *= corr0; Oacc[f][1] *= corr0;
            Oacc[f][2] *= corr1; Oacc[f][3] *= corr1;
        }

        // O += P . V : A-fragments DIRECT from QK C registers.
        // With the shared k-permutation, C layout {c0,c1;c2,c3} at cols
        // (2q4, 2q4+1) x rows (r4, r4+8) IS the permuted A layout:
        //   a = { P[r4][2q4], P[r4+8][2q4], P[r4][2q4+1], P[r4+8][2q4+1] }
        #pragma unroll
        for (int kk = 0; kk < 4; kk++) {
            uint32_t a[4] = { f2tf(s[kk][0]), f2tf(s[kk][2]),
                              f2tf(s[kk][1]), f2tf(s[kk][3]) };
            const int kr = kk * 8 + 2 * q4;
            #pragma unroll
            for (int f = 0; f < 8; f++) {
                int nc = f * 8 + r4;
                uint32_t b2[2] = { sV[kr * SV_ROW + nc], sV[(kr + 1) * SV_ROW + nc] };
                mma8(Oacc[f], a, b2);
            }
        }
    }

    // Epilogue: O / l, store ctx [B, S, H*Dh]
    float inv0 = 1.f / lrow0;
    float inv1 = 1.f / lrow1;
    int row0 = q0 + warp * 16 + r4;
    #pragma unroll
    for (int f = 0; f < 8; f++) {
        int dh = f * 8 + 2 * q4;
        size_t i0 = ((size_t)b * SQ + row0) * DM + h * DH + dh;
        size_t i8 = ((size_t)b * SQ + row0 + 8) * DM + h * DH + dh;
        *(float2*)&ctx_out[i0] = make_float2(Oacc[f][0] * inv0, Oacc[f][1] * inv0);
        *(float2*)&ctx_out[i8] = make_float2(Oacc[f][2] * inv1, Oacc[f][3] * inv1);
    }
}

extern "C" void kernel_launch(void* const* d_in, const int* in_sizes, int n_in,
                              void* d_out, int out_size) {
    const float* X    = (const float*)d_in[0];
    const float* mask = (const float*)d_in[1];
    const float* res  = (const float*)d_in[2];
    const float* Wq   = (const float*)d_in[3];
    const float* bq   = (const float*)d_in[4];
    const float* Wk   = (const float*)d_in[5];
    const float* bk   = (const float*)d_in[6];
    const float* Wv   = (const float*)d_in[7];
    const float* bv   = (const float*)d_in[8];

    float* ctx     = (float*)d_out;
    float* res_out = (float*)d_out + (size_t)NB * SQ * DM;

    dim3 g1(DM / 64, (NB * SQ) / 128, 3);
    qkv_kernel<<<g1, 256>>>(X, Wq, bq, Wk, bk, Wv, bv);

    dim3 g2(SQ / 128, NH, NB);
    attn_kernel<<<g2, 256>>>(res, mask, ctx, res_out);
}